// round 6
// baseline (speedup 1.0000x reference)
#include <cuda_runtime.h>
#include <math.h>

// ---------------------------------------------------------------------------
// Bregman divergence via 1-D tabulation with the KL log folded into the table:
//   Py(x) = F(x) + c*x*log(max(x,1e-10))
//   Gp(x) = G(x) + c
//   div   = Py(y) - Py(y0) - (Gp(y0) + c*log(max(y0,1e-10)))*dy + 0.5*a*dy^2
// F(x) = sum_j v_j*(H_j(x)-H_j(0)),  G(x) = sum_j v_j*act_j(w_j x+b_j).
// ---------------------------------------------------------------------------

#define TN     2048
#define NGRP   21
#define NNEUR  126
#define EPSF   1e-3f

__device__ float2 g_node[TN + 1];   // (Py, Gp) at node i

// -------- precompute: one block per node, one THREAD per neuron -------------
__global__ __launch_bounds__(128)
void node_kernel(const float* __restrict__ v,
                 const float* __restrict__ w,
                 const float* __restrict__ b,
                 const float* __restrict__ C) {
    int node = blockIdx.x;                       // 0..TN
    int j = threadIdx.x;                         // 0..127 (126 neurons)
    float x = (float)node * (1.0f / (float)TN);

    float accF = 0.0f, accG = 0.0f;
    if (j < NNEUR) {
        int g = j / NGRP;
        float wj = __ldg(w + j), bj = __ldg(b + j), vj = __ldg(v + j);
        bool  small = fabsf(wj) < 1e-12f;
        float rw = 1.0f / (small ? 1.0f : wj);
        float u  = fmaf(wj, x, bj);

        float act, hh;
        if (g == 0) {                            // act=u^3, H=u^4/(4w)
            float u2 = u * u;
            act = u2 * u;
            float b2 = bj * bj;
            hh = (u2 * u2 - b2 * b2) * (0.25f * rw);
        } else if (g == 1) {                     // act=u^2, H=u^3/(3w)
            float u2 = u * u;
            act = u2;
            hh = (u2 * u - bj * bj * bj) * (rw * (1.0f / 3.0f));
        } else if (g == 2) {                     // act=sqrt(u+), H=(2/3)u+^1.5/w
            float uc = fmaxf(u, 0.0f);
            float s  = sqrtf(uc);
            act = s;
            float bc = fmaxf(bj, 0.0f);
            hh = (2.0f / 3.0f) * rw * (uc * s - bc * sqrtf(bc));
        } else if (g == 3) {                     // act=u+^(1/3), H=0.75 u+^(4/3)/w
            float uc = fmaxf(u, 0.0f);
            float cb = cbrtf(uc);
            act = cb;
            float bc = fmaxf(bj, 0.0f);
            hh = 0.75f * rw * (uc * cb - bc * cbrtf(bc));
        } else if (g == 4) {                     // act=log(u+ + eps)
            float U  = fmaxf(u, 0.0f) + EPSF;
            float lu = logf(U);
            act = lu;
            if (u >= 0.0f && bj >= 0.0f) {
                float B = bj + EPSF;
                hh = fmaf(x, lu - 1.0f, (B * rw) * log1pf(wj * x / B));
            } else {
                float B  = fmaxf(bj, 0.0f) + EPSF;
                float lb = logf(B);
                hh = (U * (lu - 1.0f) - B * (lb - 1.0f)) * rw;
            }
        } else {                                 // act=exp(u), H=exp(u)/w
            float e = expf(u);
            act = e;
            float t = wj * x;
            float P = 1.0f + t * (0.5f + t * ((1.0f / 6.0f)
                          + t * ((1.0f / 24.0f) + t * (1.0f / 120.0f))));
            hh = expf(bj) * x * P;
        }
        accG = vj * act;
        accF = small ? accG * x : vj * hh;
    }

    #pragma unroll
    for (int s = 16; s > 0; s >>= 1) {
        accF += __shfl_xor_sync(0xFFFFFFFFu, accF, s);
        accG += __shfl_xor_sync(0xFFFFFFFFu, accG, s);
    }
    __shared__ float2 part[4];
    if ((j & 31) == 0) part[j >> 5] = make_float2(accF, accG);
    __syncthreads();
    if (j == 0) {
        float F = part[0].x + part[1].x + part[2].x + part[3].x;
        float G = part[0].y + part[1].y + part[2].y + part[3].y;
        float c = __ldg(C);
        float Py = fmaf(c * x, logf(fmaxf(x, 1e-10f)), F);
        g_node[node] = make_float2(Py, G + c);
    }
}

// ------------------------------- main kernel --------------------------------
__device__ __forceinline__ float bregman_elem(float y, float y0, float a, float c,
                                              const float4* __restrict__ tab) {
    float ty = y * (float)TN;
    int   iy = min((int)ty, TN - 1);
    float fy = ty - (float)iy;
    float2 ey = *(const float2*)(tab + iy);      // (Py, dPy)
    float PY = fmaf(fy, ey.y, ey.x);

    float t0 = y0 * (float)TN;
    int   i0 = min((int)t0, TN - 1);
    float f0 = t0 - (float)i0;
    float4 e0 = tab[i0];                         // (Py, dPy, Gp, dGp)
    float P0 = fmaf(f0, e0.y, e0.x);
    float G0 = fmaf(f0, e0.w, e0.z);

    float dy = y - y0;
    float L0 = __logf(fmaxf(y0, 1e-10f));
    float slope = fmaf(c, L0, G0);               // G + c + c*log(y0s)
    float d = PY - P0;
    d = fmaf(-slope, dy, d);
    d = fmaf(0.5f * a * dy, dy, d);
    return d;
}

__device__ __forceinline__ float4 bregman_vec(float4 yv, float4 y0v, float a, float c,
                                              const float4* __restrict__ tab) {
    float4 o;
    o.x = bregman_elem(yv.x, y0v.x, a, c, tab);
    o.y = bregman_elem(yv.y, y0v.y, a, c, tab);
    o.z = bregman_elem(yv.z, y0v.z, a, c, tab);
    o.w = bregman_elem(yv.w, y0v.w, a, c, tab);
    return o;
}

__global__ __launch_bounds__(256)
void main_kernel(const float4* __restrict__ Y, const float4* __restrict__ Y0,
                 const float* __restrict__ A, const float* __restrict__ C,
                 float4* __restrict__ OUT, int n4) {
    __shared__ float4 tab[TN];   // (Py0, dPy, Gp0, dGp) : 32 KB
    for (int i = threadIdx.x; i < TN; i += blockDim.x) {
        float2 n0 = g_node[i];
        float2 n1 = g_node[i + 1];
        tab[i] = make_float4(n0.x, n1.x - n0.x, n0.y, n1.y - n0.y);
    }
    __syncthreads();

    float a = __ldg(A);
    float c = __ldg(C);
    int stride = gridDim.x * blockDim.x;
    int idx = blockIdx.x * blockDim.x + threadIdx.x;

    // paired grid-stride iterations: 8 independent lookups in flight per thread
    for (; idx + stride < n4; idx += 2 * stride) {
        float4 ya  = __ldg(Y  + idx);
        float4 y0a = __ldg(Y0 + idx);
        float4 yb  = __ldg(Y  + idx + stride);
        float4 y0b = __ldg(Y0 + idx + stride);
        float4 oa = bregman_vec(ya, y0a, a, c, tab);
        float4 ob = bregman_vec(yb, y0b, a, c, tab);
        OUT[idx]          = oa;
        OUT[idx + stride] = ob;
    }
    if (idx < n4) {
        float4 yv  = __ldg(Y  + idx);
        float4 y0v = __ldg(Y0 + idx);
        OUT[idx] = bregman_vec(yv, y0v, a, c, tab);
    }
}

// scalar tail (n % 4): reads g_node directly (not launched when n%4==0)
__global__ void tail_kernel(const float* __restrict__ Y, const float* __restrict__ Y0,
                            const float* __restrict__ A, const float* __restrict__ C,
                            float* __restrict__ OUT, int start, int n) {
    int i = start + blockIdx.x * blockDim.x + threadIdx.x;
    if (i >= n) return;
    float y = Y[i], y0 = Y0[i];
    float a = __ldg(A), c = __ldg(C);

    float ty = y * (float)TN;
    int   iy = min((int)ty, TN - 1);
    float fy = ty - (float)iy;
    float2 n0 = g_node[iy], n1 = g_node[iy + 1];
    float PY = fmaf(fy, n1.x - n0.x, n0.x);

    float t0 = y0 * (float)TN;
    int   i0 = min((int)t0, TN - 1);
    float f0 = t0 - (float)i0;
    float2 m0 = g_node[i0], m1 = g_node[i0 + 1];
    float P0 = fmaf(f0, m1.x - m0.x, m0.x);
    float G0 = fmaf(f0, m1.y - m0.y, m0.y);

    float dy = y - y0;
    float L0 = logf(fmaxf(y0, 1e-10f));
    float d = PY - P0;
    d = fmaf(-fmaf(c, L0, G0), dy, d);
    d = fmaf(0.5f * a * dy, dy, d);
    OUT[i] = d;
}

// ------------------------------- launch -------------------------------------
extern "C" void kernel_launch(void* const* d_in, const int* in_sizes, int n_in,
                              void* d_out, int out_size) {
    const float* y  = (const float*)d_in[0];
    const float* y0 = (const float*)d_in[1];
    const float* v  = (const float*)d_in[2];
    const float* w  = (const float*)d_in[3];
    const float* b  = (const float*)d_in[4];
    const float* a  = (const float*)d_in[5];
    const float* c  = (const float*)d_in[6];

    node_kernel<<<TN + 1, 128>>>(v, w, b, c);

    int n  = out_size;
    int n4 = n >> 2;
    if (n4 > 0)
        main_kernel<<<888, 256>>>((const float4*)y, (const float4*)y0,
                                  a, c, (float4*)d_out, n4);
    int rem = n & 3;
    if (rem)
        tail_kernel<<<1, 32>>>(y, y0, a, c, (float*)d_out, n4 << 2, n);
}

// round 7
// speedup vs baseline: 1.1248x; 1.1248x over previous
#include <cuda_runtime.h>
#include <math.h>

// ---------------------------------------------------------------------------
// Bregman divergence via 1-D tabulation with the KL log folded into the table:
//   Py(x) = F(x) + c*x*log(max(x,1e-10))
//   Gp(x) = G(x) + c
//   div   = Py(y) - Py(y0) - (Gp(y0) + c*log(max(y0,1e-10)))*dy + 0.5*a*dy^2
// F(x) = sum_j v_j*(H_j(x)-H_j(0)),  G(x) = sum_j v_j*act_j(w_j x+b_j).
// Tables split into two float2 arrays (8B strided) to cut smem bank-conflict
// wavefronts vs the 16B-strided float4 layout (R5 profiling: smem-phase bound).
// ---------------------------------------------------------------------------

#define TN     2048
#define NGRP   21
#define NNEUR  126
#define EPSF   1e-3f

__device__ float2 g_node[TN + 1];   // (Py, Gp) at node i

// -------- precompute: one block per node, one THREAD per neuron -------------
__global__ __launch_bounds__(128)
void node_kernel(const float* __restrict__ v,
                 const float* __restrict__ w,
                 const float* __restrict__ b,
                 const float* __restrict__ C) {
    int node = blockIdx.x;                       // 0..TN
    int j = threadIdx.x;                         // 0..127 (126 neurons)
    float x = (float)node * (1.0f / (float)TN);

    float accF = 0.0f, accG = 0.0f;
    if (j < NNEUR) {
        int g = j / NGRP;
        float wj = __ldg(w + j), bj = __ldg(b + j), vj = __ldg(v + j);
        bool  small = fabsf(wj) < 1e-12f;
        float rw = 1.0f / (small ? 1.0f : wj);
        float u  = fmaf(wj, x, bj);

        float act, hh;
        if (g == 0) {                            // act=u^3, H=u^4/(4w)
            float u2 = u * u;
            act = u2 * u;
            float b2 = bj * bj;
            hh = (u2 * u2 - b2 * b2) * (0.25f * rw);
        } else if (g == 1) {                     // act=u^2, H=u^3/(3w)
            float u2 = u * u;
            act = u2;
            hh = (u2 * u - bj * bj * bj) * (rw * (1.0f / 3.0f));
        } else if (g == 2) {                     // act=sqrt(u+), H=(2/3)u+^1.5/w
            float uc = fmaxf(u, 0.0f);
            float s  = sqrtf(uc);
            act = s;
            float bc = fmaxf(bj, 0.0f);
            hh = (2.0f / 3.0f) * rw * (uc * s - bc * sqrtf(bc));
        } else if (g == 3) {                     // act=u+^(1/3), H=0.75 u+^(4/3)/w
            float uc = fmaxf(u, 0.0f);
            float cb = cbrtf(uc);
            act = cb;
            float bc = fmaxf(bj, 0.0f);
            hh = 0.75f * rw * (uc * cb - bc * cbrtf(bc));
        } else if (g == 4) {                     // act=log(u+ + eps)
            float U  = fmaxf(u, 0.0f) + EPSF;
            float lu = logf(U);
            act = lu;
            if (u >= 0.0f && bj >= 0.0f) {
                float B = bj + EPSF;
                hh = fmaf(x, lu - 1.0f, (B * rw) * log1pf(wj * x / B));
            } else {
                float B  = fmaxf(bj, 0.0f) + EPSF;
                float lb = logf(B);
                hh = (U * (lu - 1.0f) - B * (lb - 1.0f)) * rw;
            }
        } else {                                 // act=exp(u), H=exp(u)/w
            float e = expf(u);
            act = e;
            float t = wj * x;
            float P = 1.0f + t * (0.5f + t * ((1.0f / 6.0f)
                          + t * ((1.0f / 24.0f) + t * (1.0f / 120.0f))));
            hh = expf(bj) * x * P;
        }
        accG = vj * act;
        accF = small ? accG * x : vj * hh;
    }

    #pragma unroll
    for (int s = 16; s > 0; s >>= 1) {
        accF += __shfl_xor_sync(0xFFFFFFFFu, accF, s);
        accG += __shfl_xor_sync(0xFFFFFFFFu, accG, s);
    }
    __shared__ float2 part[4];
    if ((j & 31) == 0) part[j >> 5] = make_float2(accF, accG);
    __syncthreads();
    if (j == 0) {
        float F = part[0].x + part[1].x + part[2].x + part[3].x;
        float G = part[0].y + part[1].y + part[2].y + part[3].y;
        float c = __ldg(C);
        float Py = fmaf(c * x, logf(fmaxf(x, 1e-10f)), F);
        g_node[node] = make_float2(Py, G + c);
    }
}

// ------------------------------- main kernel --------------------------------
__device__ __forceinline__ float bregman_elem(float y, float y0, float a, float c,
                                              const float2* __restrict__ TP,
                                              const float2* __restrict__ TG) {
    float ty = y * (float)TN;
    int   iy = min((int)ty, TN - 1);
    float fy = ty - (float)iy;

    float t0 = y0 * (float)TN;
    int   i0 = min((int)t0, TN - 1);
    float f0 = t0 - (float)i0;

    float2 ey = TP[iy];                          // (Py, dPy) for y
    float2 e0 = TP[i0];                          // (Py, dPy) for y0
    float2 g0 = TG[i0];                          // (Gp, dGp) for y0

    float PY = fmaf(fy, ey.y, ey.x);
    float P0 = fmaf(f0, e0.y, e0.x);
    float G0 = fmaf(f0, g0.y, g0.x);

    float dy = y - y0;
    float L0 = __logf(fmaxf(y0, 1e-10f));
    float slope = fmaf(c, L0, G0);               // G + c + c*log(y0s)
    float d = PY - P0;
    d = fmaf(-slope, dy, d);
    d = fmaf(0.5f * a * dy, dy, d);
    return d;
}

__global__ __launch_bounds__(256, 6)
void main_kernel(const float4* __restrict__ Y, const float4* __restrict__ Y0,
                 const float* __restrict__ A, const float* __restrict__ C,
                 float4* __restrict__ OUT, int n4) {
    __shared__ float2 TP[TN];    // (Py0, dPy) : 16 KB
    __shared__ float2 TG[TN];    // (Gp0, dGp) : 16 KB
    for (int i = threadIdx.x; i < TN; i += blockDim.x) {
        float2 n0 = g_node[i];
        float2 n1 = g_node[i + 1];
        TP[i] = make_float2(n0.x, n1.x - n0.x);
        TG[i] = make_float2(n0.y, n1.y - n0.y);
    }
    __syncthreads();

    float a = __ldg(A);
    float c = __ldg(C);
    int stride = gridDim.x * blockDim.x;
    for (int idx = blockIdx.x * blockDim.x + threadIdx.x; idx < n4; idx += stride) {
        float4 yv  = __ldg(Y  + idx);
        float4 y0v = __ldg(Y0 + idx);
        float4 o;
        o.x = bregman_elem(yv.x, y0v.x, a, c, TP, TG);
        o.y = bregman_elem(yv.y, y0v.y, a, c, TP, TG);
        o.z = bregman_elem(yv.z, y0v.z, a, c, TP, TG);
        o.w = bregman_elem(yv.w, y0v.w, a, c, TP, TG);
        OUT[idx] = o;
    }
}

// scalar tail (n % 4): reads g_node directly (not launched when n%4==0)
__global__ void tail_kernel(const float* __restrict__ Y, const float* __restrict__ Y0,
                            const float* __restrict__ A, const float* __restrict__ C,
                            float* __restrict__ OUT, int start, int n) {
    int i = start + blockIdx.x * blockDim.x + threadIdx.x;
    if (i >= n) return;
    float y = Y[i], y0 = Y0[i];
    float a = __ldg(A), c = __ldg(C);

    float ty = y * (float)TN;
    int   iy = min((int)ty, TN - 1);
    float fy = ty - (float)iy;
    float2 n0 = g_node[iy], n1 = g_node[iy + 1];
    float PY = fmaf(fy, n1.x - n0.x, n0.x);

    float t0 = y0 * (float)TN;
    int   i0 = min((int)t0, TN - 1);
    float f0 = t0 - (float)i0;
    float2 m0 = g_node[i0], m1 = g_node[i0 + 1];
    float P0 = fmaf(f0, m1.x - m0.x, m0.x);
    float G0 = fmaf(f0, m1.y - m0.y, m0.y);

    float dy = y - y0;
    float L0 = logf(fmaxf(y0, 1e-10f));
    float d = PY - P0;
    d = fmaf(-fmaf(c, L0, G0), dy, d);
    d = fmaf(0.5f * a * dy, dy, d);
    OUT[i] = d;
}

// ------------------------------- launch -------------------------------------
extern "C" void kernel_launch(void* const* d_in, const int* in_sizes, int n_in,
                              void* d_out, int out_size) {
    const float* y  = (const float*)d_in[0];
    const float* y0 = (const float*)d_in[1];
    const float* v  = (const float*)d_in[2];
    const float* w  = (const float*)d_in[3];
    const float* b  = (const float*)d_in[4];
    const float* a  = (const float*)d_in[5];
    const float* c  = (const float*)d_in[6];

    node_kernel<<<TN + 1, 128>>>(v, w, b, c);

    int n  = out_size;
    int n4 = n >> 2;
    if (n4 > 0)
        main_kernel<<<888, 256>>>((const float4*)y, (const float4*)y0,
                                  a, c, (float4*)d_out, n4);
    int rem = n & 3;
    if (rem)
        tail_kernel<<<1, 32>>>(y, y0, a, c, (float*)d_out, n4 << 2, n);
}

// round 8
// speedup vs baseline: 1.1270x; 1.0020x over previous
#include <cuda_runtime.h>
#include <math.h>

// ---------------------------------------------------------------------------
// Bregman divergence via 1-D tabulation with the KL log folded into the table:
//   Py(x) = F(x) + c*x*log(max(x,1e-10))
//   Gp(x) = G(x) + c
//   div   = Py(y) - Py(y0) - (Gp(y0) + c*log(max(y0,1e-10)))*dy + 0.5*a*dy^2
// F(x) = sum_j v_j*(H_j(x)-H_j(0)),  G(x) = sum_j v_j*act_j(w_j x+b_j).
// Main kernel: float4 table in smem, one clean 5-block/SM wave (grid 740),
// 2-stage software-pipelined grid-stride loop (prefetch next LDGs).
// ---------------------------------------------------------------------------

#define TN     2048
#define NGRP   21
#define NNEUR  126
#define EPSF   1e-3f

__device__ float2 g_node[TN + 1];   // (Py, Gp) at node i

// -------- precompute: one block per node, one THREAD per neuron -------------
__global__ __launch_bounds__(128)
void node_kernel(const float* __restrict__ v,
                 const float* __restrict__ w,
                 const float* __restrict__ b,
                 const float* __restrict__ C) {
    int node = blockIdx.x;                       // 0..TN
    int j = threadIdx.x;                         // 0..127 (126 neurons)
    float x = (float)node * (1.0f / (float)TN);

    float accF = 0.0f, accG = 0.0f;
    if (j < NNEUR) {
        int g = j / NGRP;
        float wj = __ldg(w + j), bj = __ldg(b + j), vj = __ldg(v + j);
        bool  small = fabsf(wj) < 1e-12f;
        float rw = 1.0f / (small ? 1.0f : wj);
        float u  = fmaf(wj, x, bj);

        float act, hh;
        if (g == 0) {                            // act=u^3, H=u^4/(4w)
            float u2 = u * u;
            act = u2 * u;
            float b2 = bj * bj;
            hh = (u2 * u2 - b2 * b2) * (0.25f * rw);
        } else if (g == 1) {                     // act=u^2, H=u^3/(3w)
            float u2 = u * u;
            act = u2;
            hh = (u2 * u - bj * bj * bj) * (rw * (1.0f / 3.0f));
        } else if (g == 2) {                     // act=sqrt(u+), H=(2/3)u+^1.5/w
            float uc = fmaxf(u, 0.0f);
            float s  = sqrtf(uc);
            act = s;
            float bc = fmaxf(bj, 0.0f);
            hh = (2.0f / 3.0f) * rw * (uc * s - bc * sqrtf(bc));
        } else if (g == 3) {                     // act=u+^(1/3), H=0.75 u+^(4/3)/w
            float uc = fmaxf(u, 0.0f);
            float cb = cbrtf(uc);
            act = cb;
            float bc = fmaxf(bj, 0.0f);
            hh = 0.75f * rw * (uc * cb - bc * cbrtf(bc));
        } else if (g == 4) {                     // act=log(u+ + eps)
            float U  = fmaxf(u, 0.0f) + EPSF;
            float lu = logf(U);
            act = lu;
            if (u >= 0.0f && bj >= 0.0f) {
                float B = bj + EPSF;
                hh = fmaf(x, lu - 1.0f, (B * rw) * log1pf(wj * x / B));
            } else {
                float B  = fmaxf(bj, 0.0f) + EPSF;
                float lb = logf(B);
                hh = (U * (lu - 1.0f) - B * (lb - 1.0f)) * rw;
            }
        } else {                                 // act=exp(u), H=exp(u)/w
            float e = expf(u);
            act = e;
            float t = wj * x;
            float P = 1.0f + t * (0.5f + t * ((1.0f / 6.0f)
                          + t * ((1.0f / 24.0f) + t * (1.0f / 120.0f))));
            hh = expf(bj) * x * P;
        }
        accG = vj * act;
        accF = small ? accG * x : vj * hh;
    }

    #pragma unroll
    for (int s = 16; s > 0; s >>= 1) {
        accF += __shfl_xor_sync(0xFFFFFFFFu, accF, s);
        accG += __shfl_xor_sync(0xFFFFFFFFu, accG, s);
    }
    __shared__ float2 part[4];
    if ((j & 31) == 0) part[j >> 5] = make_float2(accF, accG);
    __syncthreads();
    if (j == 0) {
        float F = part[0].x + part[1].x + part[2].x + part[3].x;
        float G = part[0].y + part[1].y + part[2].y + part[3].y;
        float c = __ldg(C);
        float Py = fmaf(c * x, logf(fmaxf(x, 1e-10f)), F);
        g_node[node] = make_float2(Py, G + c);
    }
}

// ------------------------------- main kernel --------------------------------
__device__ __forceinline__ float bregman_elem(float y, float y0, float a, float c,
                                              const float4* __restrict__ tab) {
    float ty = y * (float)TN;
    int   iy = min((int)ty, TN - 1);
    float fy = ty - (float)iy;
    float2 ey = *(const float2*)(tab + iy);      // (Py, dPy) for y
    float PY = fmaf(fy, ey.y, ey.x);

    float t0 = y0 * (float)TN;
    int   i0 = min((int)t0, TN - 1);
    float f0 = t0 - (float)i0;
    float4 e0 = tab[i0];                         // (Py, dPy, Gp, dGp)
    float P0 = fmaf(f0, e0.y, e0.x);
    float G0 = fmaf(f0, e0.w, e0.z);

    float dy = y - y0;
    float L0 = __logf(fmaxf(y0, 1e-10f));
    float slope = fmaf(c, L0, G0);               // G + c + c*log(y0s)
    float d = PY - P0;
    d = fmaf(-slope, dy, d);
    d = fmaf(0.5f * a * dy, dy, d);
    return d;
}

__device__ __forceinline__ float4 bregman_vec(float4 yv, float4 y0v, float a, float c,
                                              const float4* __restrict__ tab) {
    float4 o;
    o.x = bregman_elem(yv.x, y0v.x, a, c, tab);
    o.y = bregman_elem(yv.y, y0v.y, a, c, tab);
    o.z = bregman_elem(yv.z, y0v.z, a, c, tab);
    o.w = bregman_elem(yv.w, y0v.w, a, c, tab);
    return o;
}

#define MAIN_GRID  740   // 148 SMs x 5 blocks: exactly one wave
#define MAIN_BLK   256

__global__ __launch_bounds__(MAIN_BLK, 5)
void main_kernel(const float4* __restrict__ Y, const float4* __restrict__ Y0,
                 const float* __restrict__ A, const float* __restrict__ C,
                 float4* __restrict__ OUT, int n4) {
    __shared__ float4 tab[TN];   // (Py0, dPy, Gp0, dGp) : 32 KB
    for (int i = threadIdx.x; i < TN; i += blockDim.x) {
        float2 n0 = g_node[i];
        float2 n1 = g_node[i + 1];
        tab[i] = make_float4(n0.x, n1.x - n0.x, n0.y, n1.y - n0.y);
    }
    __syncthreads();

    float a = __ldg(A);
    float c = __ldg(C);
    const int stride = MAIN_GRID * MAIN_BLK;
    int idx = blockIdx.x * MAIN_BLK + threadIdx.x;

    if (idx >= n4) return;

    // 2-stage software pipeline: next iteration's LDGs issue before current math
    float4 ya  = __ldg(Y  + idx);
    float4 y0a = __ldg(Y0 + idx);
    int nidx = idx + stride;
    while (nidx < n4) {
        float4 yb  = __ldg(Y  + nidx);
        float4 y0b = __ldg(Y0 + nidx);
        OUT[idx] = bregman_vec(ya, y0a, a, c, tab);
        ya = yb; y0a = y0b;
        idx = nidx;
        nidx = idx + stride;
    }
    OUT[idx] = bregman_vec(ya, y0a, a, c, tab);
}

// scalar tail (n % 4): reads g_node directly (not launched when n%4==0)
__global__ void tail_kernel(const float* __restrict__ Y, const float* __restrict__ Y0,
                            const float* __restrict__ A, const float* __restrict__ C,
                            float* __restrict__ OUT, int start, int n) {
    int i = start + blockIdx.x * blockDim.x + threadIdx.x;
    if (i >= n) return;
    float y = Y[i], y0 = Y0[i];
    float a = __ldg(A), c = __ldg(C);

    float ty = y * (float)TN;
    int   iy = min((int)ty, TN - 1);
    float fy = ty - (float)iy;
    float2 n0 = g_node[iy], n1 = g_node[iy + 1];
    float PY = fmaf(fy, n1.x - n0.x, n0.x);

    float t0 = y0 * (float)TN;
    int   i0 = min((int)t0, TN - 1);
    float f0 = t0 - (float)i0;
    float2 m0 = g_node[i0], m1 = g_node[i0 + 1];
    float P0 = fmaf(f0, m1.x - m0.x, m0.x);
    float G0 = fmaf(f0, m1.y - m0.y, m0.y);

    float dy = y - y0;
    float L0 = logf(fmaxf(y0, 1e-10f));
    float d = PY - P0;
    d = fmaf(-fmaf(c, L0, G0), dy, d);
    d = fmaf(0.5f * a * dy, dy, d);
    OUT[i] = d;
}

// ------------------------------- launch -------------------------------------
extern "C" void kernel_launch(void* const* d_in, const int* in_sizes, int n_in,
                              void* d_out, int out_size) {
    const float* y  = (const float*)d_in[0];
    const float* y0 = (const float*)d_in[1];
    const float* v  = (const float*)d_in[2];
    const float* w  = (const float*)d_in[3];
    const float* b  = (const float*)d_in[4];
    const float* a  = (const float*)d_in[5];
    const float* c  = (const float*)d_in[6];

    node_kernel<<<TN + 1, 128>>>(v, w, b, c);

    int n  = out_size;
    int n4 = n >> 2;
    if (n4 > 0)
        main_kernel<<<MAIN_GRID, MAIN_BLK>>>((const float4*)y, (const float4*)y0,
                                             a, c, (float4*)d_out, n4);
    int rem = n & 3;
    if (rem)
        tail_kernel<<<1, 32>>>(y, y0, a, c, (float*)d_out, n4 << 2, n);
}